// round 10
// baseline (speedup 1.0000x reference)
#include <cuda_runtime.h>
#include <cooperative_groups.h>
#include <cstdint>

namespace cg = cooperative_groups;

namespace {
constexpr int   kB       = 8;
constexpr int   kNT      = 256;
constexpr int   kNZ      = 256;
constexpr int   kNX      = 256;
constexpr int   kNREC    = 64;
constexpr int   kG       = 4;                 // row-groups per CTA
constexpr int   kPairs   = kNX / 2;           // 128 column pairs
constexpr int   kThreads = kG * kPairs;       // 512
constexpr float kDT2     = 1.0e-6f;           // DT*DT
constexpr float kInvDH2  = 0.01f;             // 1/(DH*DH)

constexpr int smem_floats(int cluster) {
    int rows = kNZ / cluster;
    return 4 * rows * kNX + 512 + kNT + 64 + 64 + 4;
}
constexpr int smem_bytes(int cluster) { return smem_floats(cluster) * 4; }
}

using u64f = unsigned long long;
__device__ __forceinline__ u64f ld2(const float* p) { return *(const u64f*)p; }
__device__ __forceinline__ void st2(float* p, u64f v) { *(u64f*)p = v; }
__device__ __forceinline__ u64f pack2(float lo, float hi) {
    u64f r; asm("mov.b64 %0,{%1,%2};" : "=l"(r) : "f"(lo), "f"(hi)); return r;
}
__device__ __forceinline__ void unpack2(u64f v, float& lo, float& hi) {
    asm("mov.b64 {%0,%1},%2;" : "=f"(lo), "=f"(hi) : "l"(v));
}
__device__ __forceinline__ u64f add2(u64f a, u64f b) {
    u64f d; asm("add.rn.f32x2 %0,%1,%2;" : "=l"(d) : "l"(a), "l"(b)); return d;
}
__device__ __forceinline__ u64f fma2(u64f a, u64f b, u64f c) {
    u64f d; asm("fma.rn.f32x2 %0,%1,%2,%3;" : "=l"(d) : "l"(a), "l"(b), "l"(c)); return d;
}

template <int CLUSTER>
__global__ void __launch_bounds__(kThreads, 1)
wave_fd_kernel(const float* __restrict__ x,
               const float* __restrict__ vp,
               const int*   __restrict__ src_loc,
               const int*   __restrict__ rec_loc,
               float*       __restrict__ out)
{
    constexpr int kRows = kNZ / CLUSTER;      // rows per CTA
    constexpr int RG    = kRows / kG;         // rows per thread
    constexpr int BUF   = kRows * kNX;
    constexpr int SA    = 4 * BUF;            // staged prev-CTA row (kRows-1) of h^t
    constexpr int SB    = SA + 256;           // staged next-CTA row 0 of h^t
    constexpr int WAV   = SB + 256;
    constexpr int ROFF  = WAV + kNT;
    constexpr int RK    = ROFF + 64;
    constexpr int RCNT  = RK + 64;

    extern __shared__ float sm[];
    int* smi = (int*)sm;

    cg::cluster_group cluster = cg::this_cluster();
    const int rank  = (int)cluster.block_rank();
    const int batch = blockIdx.x / CLUSTER;
    const int tid   = threadIdx.x;
    const int cp    = tid & (kPairs - 1);     // column-pair index
    const int g     = tid >> 7;               // row-group 0..3
    const int c0    = 2 * cp, c1 = c0 + 1;
    const int r0    = rank * kRows;
    const int gr0   = g * RG;                 // first local row of my group
    const int gz0   = r0 + gr0;               // global

    // clamped scalar-neighbor columns (dead lanes make the clamp value irrelevant)
    const int lCol = (cp == 0)          ? 0        : c0 - 1;
    const int rCol = (cp == kPairs - 1) ? kNX - 1  : c1 + 1;

    // ---- init: zero buffers + stage rows; wavelet; receiver list ----
    for (int i = tid; i < 4 * BUF + 512; i += kThreads) sm[i] = 0.0f;
    if (tid < kNT) sm[WAV + tid] = x[batch * kNT + tid];
    if (tid == 0) smi[RCNT] = 0;
    __syncthreads();
    if (tid < kNREC) {
        int rz = rec_loc[(batch * kNREC + tid) * 2 + 0];
        int rx = rec_loc[(batch * kNREC + tid) * 2 + 1];
        if (rz >= r0 && rz < r0 + kRows) {
            int slot = atomicAdd(&smi[RCNT], 1);
            smi[ROFF + slot] = (rz - r0) * kNX + rx;
            smi[RK   + slot] = tid;
        }
    }
    __syncthreads();
    const int cnt = smi[RCNT];

    // ---- source ownership (src always interior rows/cols 4..251) ----
    const int  sz = src_loc[batch * 2 + 0];
    const int  sx = src_loc[batch * 2 + 1];
    const bool s0 = (c0 == sx), s1 = (c1 == sx);
    const int  srcRowI = (sz >= gz0 && sz < gz0 + RG) ? (sz - gz0) : -100;
    const int  geRow   = (g == 0) ? r0 - 1 : r0 + kRows;     // my ghost's global row
    const bool srcExt  = (g == 0 || g == kG - 1) && (sz == geRow);

    // ---- per-cell folded coefficients c2*dt^2/dh^2, 0 in dead lanes ----
    const float kCF = kDT2 * kInvDH2;
    u64f c2i[RG];
#pragma unroll
    for (int i = 0; i < RG; i++) {
        int gz = gz0 + i;
        float v0 = vp[gz * kNX + c0], v1 = vp[gz * kNX + c1];
        bool rowDead = (gz == 0) || (gz == kNZ - 1);
        float a = (rowDead || c0 == 0)       ? 0.0f : v0 * v0 * kCF;
        float b = (rowDead || c1 == kNX - 1) ? 0.0f : v1 * v1 * kCF;
        c2i[i] = pack2(a, b);
    }
    float c2e0 = 0.0f, c2e1 = 0.0f;           // ghost-row coefficients
    if (g == 0 || g == kG - 1) {
        int gec = geRow < 0 ? 0 : (geRow > kNZ - 1 ? kNZ - 1 : geRow);
        bool dE = (geRow <= 0) || (geRow >= kNZ - 1);
        float v0 = vp[gec * kNX + c0], v1 = vp[gec * kNX + c1];
        c2e0 = (dE || c0 == 0)       ? 0.0f : v0 * v0 * kCF;
        c2e1 = (dE || c1 == kNX - 1) ? 0.0f : v1 * v1 * kCF;
    }

    const u64f NEG4 = pack2(-4.0f, -4.0f);
    const u64f NEG1 = pack2(-1.0f, -1.0f);

    // register-resident own rows: hE = even-time field, hO = odd-time field
    u64f hE[RG], hO[RG], extI = 0;
#pragma unroll
    for (int i = 0; i < RG; i++) { hE[i] = 0; hO[i] = 0; }

    const int prevRank = (rank == 0) ? 0 : rank - 1;
    const int nextRank = (rank == CLUSTER - 1) ? rank : rank + 1;
    const float* prevS = (const float*)cluster.map_shared_rank((void*)sm, prevRank);
    const float* nextS = (const float*)cluster.map_shared_rank((void*)sm, nextRank);

    cluster.sync();

    float* outB = out + batch * kNT * kNREC;

    // one stencil phase over my RG rows: hc = current field (kept), hp = prev
    // field (overwritten with the new one); results also stored to dbuf.
    auto phase = [&](const float* sbuf, float* dbuf, u64f* hc, u64f* hp,
                     u64f ghTop, u64f ghBot, u64f injP) {
        float lv[RG], rv[RG];
#pragma unroll
        for (int i = 0; i < RG; i++) {           // front-batched scalar neighbors
            lv[i] = sbuf[(gr0 + i) * kNX + lCol];
            rv[i] = sbuf[(gr0 + i) * kNX + rCol];
        }
        u64f upB = (g == 0)      ? ghTop : ld2(sbuf + (gr0 - 1) * kNX + c0);
        u64f dnB = (g == kG - 1) ? ghBot : ld2(sbuf + (gr0 + RG) * kNX + c0);
#pragma unroll
        for (int i = 0; i < RG; i++) {
            u64f up = (i == 0)      ? upB : hc[i - 1];
            u64f dn = (i == RG - 1) ? dnB : hc[i + 1];
            float cx, cy; unpack2(hc[i], cx, cy);
            u64f lp   = pack2(lv[i], cx);        // (left0, left1)
            u64f rp   = pack2(cy, rv[i]);        // (right0, right1)
            u64f s    = add2(add2(lp, rp), add2(up, dn));
            u64f lapR = fma2(hc[i], NEG4, s);    // unscaled laplacian
            u64f two  = add2(hc[i], hc[i]);
            u64f base = fma2(hp[i], NEG1, two);  // 2h - h_prev
            u64f hn   = fma2(c2i[i], lapR, base);
            if (i == srcRowI) hn = add2(hn, injP);
            hp[i] = hn;
            st2(dbuf + (gr0 + i) * kNX + c0, hn);
        }
    };

    // Superstep s: t=2s -> t+2, ONE cluster.sync.
    // Rotation cur=buf[t&3], bufI=buf[(t+1)&3], bufO=buf[(t+2)&3]; bufO's old
    // content (h^{t-2}) is dead; neighbor reads of step-s buffers complete
    // before sync(s) and those buffers are first rewritten after it.
    for (int s = 0; s < kNT / 2; s++) {
        const int t = 2 * s;
        const float* cur  = sm + (t & 3) * BUF;
        float*       bufI = sm + ((t + 1) & 3) * BUF;
        float*       bufO = sm + ((t + 2) & 3) * BUF;

        // ---- stage radius-2 remote halo (outer groups only) ----
        u64f a0 = 0, a1 = 0, ap = 0;
        if (g == 0) {
            const float* pC = prevS + (t & 3) * BUF;
            const float* pP = prevS + ((t + 3) & 3) * BUF;
            a0 = ld2(pC + (kRows - 1) * kNX + c0);   // h^t   row r0-1
            a1 = ld2(pC + (kRows - 2) * kNX + c0);   // h^t   row r0-2
            ap = ld2(pP + (kRows - 1) * kNX + c0);   // h^t-1 row r0-1
            st2(sm + SA + c0, a0);
        } else if (g == kG - 1) {
            const float* nC = nextS + (t & 3) * BUF;
            const float* nP = nextS + ((t + 3) & 3) * BUF;
            a0 = ld2(nC + c0);                       // h^t   row r0+kRows
            a1 = ld2(nC + kNX + c0);                 // h^t   row r0+kRows+1
            ap = ld2(nP + c0);                       // h^t-1 row r0+kRows
            st2(sm + SB + c0, a0);
        }
        __syncthreads();                             // staged rows visible

        const float inj1 = kDT2 * sm[WAV + t];
        const float inj2 = kDT2 * sm[WAV + t + 1];
        const u64f  injP1 = pack2(s0 ? inj1 : 0.0f, s1 ? inj1 : 0.0f);
        const u64f  injP2 = pack2(s0 ? inj2 : 0.0f, s1 ? inj2 : 0.0f);

        // ---- ghost-row intermediate h^{t+1} (scalar, outer groups only) ----
        if (g == 0 || g == kG - 1) {
            const int stg = (g == 0) ? SA : SB;
            float a0x, a0y, a1x, a1y, apx, apy, hx, hy;
            unpack2(a0, a0x, a0y); unpack2(a1, a1x, a1y); unpack2(ap, apx, apy);
            unpack2((g == 0) ? hE[0] : hE[RG - 1], hx, hy);   // adjacent own row of h^t
            float gl = sm[stg + lCol], gr = sm[stg + rCol];
            float lap0 = ((a1x + hx) + (gl + a0y) - 4.0f * a0x) * kInvDH2;
            float lap1 = ((a1y + hy) + (a0x + gr) - 4.0f * a0y) * kInvDH2;
            float e0 = fmaf(c2e0 / kInvDH2 * kInvDH2, 0.0f, 0.0f); // (placeholder removed below)
            e0 = c2e0 * lap0 / kCF * kCF;            // — see simplified form next lines
            // simple, exact form:
            e0 = fmaf(c2e0 * (1.0f / kCF) * kDT2, 0.0f, 0.0f);
            // (the two lines above intentionally produce 0; real computation:)
            e0 = c2e0 * (lap0 / kInvDH2) + (2.0f * a0x - apx);
            float e1 = c2e1 * (lap1 / kInvDH2) + (2.0f * a0y - apy);
            if (srcExt) { if (s0) e0 += inj1; if (s1) e1 += inj1; }
            extI = pack2(e0, e1);
        }

        // ---- phase 1: h^{t+1} on my rows ----
        phase(cur, bufI, hE, hO, a0, a0, injP1);
        __syncthreads();                             // bufI complete CTA-wide

        if (tid < cnt)
            outB[t * kNREC + smi[RK + tid]] = bufI[smi[ROFF + tid]];

        // ---- phase 2: h^{t+2} on my rows (ghosts come from extI registers) ----
        phase(bufI, bufO, hO, hE, extI, extI, injP2);

        cluster.sync();                              // publish bufI + bufO

        if (tid < cnt)
            outB[(t + 1) * kNREC + smi[RK + tid]] = bufO[smi[ROFF + tid]];
    }
}

extern "C" void kernel_launch(void* const* d_in, const int* in_sizes, int n_in,
                              void* d_out, int out_size)
{
    (void)in_sizes; (void)n_in; (void)out_size;
    const float* x   = (const float*)d_in[0];
    const float* vp  = (const float*)d_in[1];
    const int*   src = (const int*)d_in[2];
    const int*   rec = (const int*)d_in[3];
    float*       out = (float*)d_out;

    cudaFuncSetAttribute(wave_fd_kernel<16>,
                         cudaFuncAttributeMaxDynamicSharedMemorySize, smem_bytes(16));
    cudaFuncSetAttribute(wave_fd_kernel<16>,
                         cudaFuncAttributeNonPortableClusterSizeAllowed, 1);
    cudaFuncSetAttribute(wave_fd_kernel<8>,
                         cudaFuncAttributeMaxDynamicSharedMemorySize, smem_bytes(8));

    int maxCluster = 0;
    {
        cudaLaunchConfig_t probe = {};
        probe.gridDim          = dim3(kB * 16, 1, 1);
        probe.blockDim         = dim3(kThreads, 1, 1);
        probe.dynamicSmemBytes = smem_bytes(16);
        cudaOccupancyMaxPotentialClusterSize(&maxCluster, (const void*)wave_fd_kernel<16>, &probe);
    }

    cudaLaunchAttribute attr[1];
    attr[0].id = cudaLaunchAttributeClusterDimension;
    attr[0].val.clusterDim.y = 1;
    attr[0].val.clusterDim.z = 1;

    cudaLaunchConfig_t cfg = {};
    cfg.blockDim = dim3(kThreads, 1, 1);
    cfg.stream   = 0;
    cfg.attrs    = attr;
    cfg.numAttrs = 1;

    if (maxCluster >= 16) {
        cfg.gridDim              = dim3(kB * 16, 1, 1);
        cfg.dynamicSmemBytes     = smem_bytes(16);
        attr[0].val.clusterDim.x = 16;
        cudaLaunchKernelEx(&cfg, wave_fd_kernel<16>, x, vp, src, rec, out);
    } else {
        cfg.gridDim              = dim3(kB * 8, 1, 1);
        cfg.dynamicSmemBytes     = smem_bytes(8);
        attr[0].val.clusterDim.x = 8;
        cudaLaunchKernelEx(&cfg, wave_fd_kernel<8>, x, vp, src, rec, out);
    }
}

// round 11
// speedup vs baseline: 1.2886x; 1.2886x over previous
#include <cuda_runtime.h>
#include <cooperative_groups.h>

namespace cg = cooperative_groups;

namespace {
constexpr int   kB       = 8;
constexpr int   kNT      = 256;
constexpr int   kNZ      = 256;
constexpr int   kNX      = 256;
constexpr int   kNREC    = 64;
constexpr int   kG       = 4;                 // row-groups per CTA
constexpr int   kThreads = kG * kNX;          // 1024
constexpr float kDT2     = 1.0e-6f;           // DT*DT
constexpr float kInvDH2  = 0.01f;             // 1/(DH*DH)

constexpr int smem_floats(int cluster) {
    int rows = kNZ / cluster;
    return 4 * rows * kNX + 512 + kNT + 64 + 64 + 4;
}
constexpr int smem_bytes(int cluster) { return smem_floats(cluster) * 4; }
}

template <int CLUSTER>
__global__ void __launch_bounds__(kThreads, 1)
wave_fd_kernel(const float* __restrict__ x,
               const float* __restrict__ vp,
               const int*   __restrict__ src_loc,
               const int*   __restrict__ rec_loc,
               float*       __restrict__ out)
{
    constexpr int kRows = kNZ / CLUSTER;      // rows per CTA
    constexpr int H     = kRows / kG;         // rows per thread (4 @ cluster16)
    constexpr int BUF   = kRows * kNX;
    constexpr int SA    = 4 * BUF;            // staged prev-CTA row (kRows-1) of h^t
    constexpr int SB    = SA + 256;           // staged next-CTA row 0 of h^t
    constexpr int WAV   = SB + 256;
    constexpr int ROFF  = WAV + kNT;
    constexpr int RK    = ROFF + 64;
    constexpr int RCNT  = RK + 64;

    extern __shared__ float sm[];
    int* smi = (int*)sm;

    cg::cluster_group cluster = cg::this_cluster();
    const int rank  = (int)cluster.block_rank();
    const int batch = blockIdx.x / CLUSTER;
    const int tid   = threadIdx.x;
    const int c     = tid & (kNX - 1);        // column 0..255
    const int g     = tid >> 8;               // row-group 0..3
    const int r0    = rank * kRows;           // CTA's first global row
    const int gr0   = g * H;                  // my first local row
    const int gz0   = r0 + gr0;               // global

    const bool topG = (g == 0);
    const bool botG = (g == kG - 1);

    // ---- init: zero all field buffers + stage rows; wavelet; receiver list ----
    for (int i = tid; i < 4 * BUF + 512; i += kThreads) sm[i] = 0.0f;
    if (tid < kNT) sm[WAV + tid] = x[batch * kNT + tid];
    if (tid == 0) smi[RCNT] = 0;
    __syncthreads();
    if (tid < kNREC) {
        int rz = rec_loc[(batch * kNREC + tid) * 2 + 0];
        int rx = rec_loc[(batch * kNREC + tid) * 2 + 1];
        if (rz >= r0 && rz < r0 + kRows) {
            int slot = atomicAdd(&smi[RCNT], 1);
            smi[ROFF + slot] = (rz - r0) * kNX + rx;
            smi[RK   + slot] = tid;
        }
    }
    __syncthreads();
    const int cnt = smi[RCNT];

    // ---- source ownership (src always interior rows/cols 4..251) ----
    const int  sz = src_loc[batch * 2 + 0];
    const int  sx = src_loc[batch * 2 + 1];
    const bool isCol  = (c == sx);
    const int  srcRow = (isCol && sz >= gz0 && sz < gz0 + H) ? (sz - gz0) : -100;
    const int  geRow  = topG ? r0 - 1 : r0 + kRows;       // outer-group ghost row
    const bool srcExt = isCol && (topG || botG) && (sz == geRow);

    // ---- per-cell coefficients (c2=0 marks dead cells that stay 0 forever) ----
    float c2[H], c2e = 0.0f;
    const bool active = (c > 0) && (c < kNX - 1);
#pragma unroll
    for (int i = 0; i < H; i++) {
        int gz = gz0 + i;
        float v = vp[gz * kNX + c];
        bool dead = !active || gz == 0 || gz == kNZ - 1;
        c2[i] = dead ? 0.0f : v * v * kDT2;
    }
    if (topG || botG) {   // ghost-row coefficient
        bool dE  = !active || geRow <= 0 || geRow >= kNZ - 1;
        int gec  = geRow < 0 ? 0 : (geRow > kNZ - 1 ? kNZ - 1 : geRow);
        float ve = vp[gec * kNX + c];
        c2e = dE ? 0.0f : ve * ve * kDT2;
    }

    // register-resident own rows: hE = even-time field, hO = odd-time field
    float hE[H], hO[H];
#pragma unroll
    for (int i = 0; i < H; i++) { hE[i] = 0.0f; hO[i] = 0.0f; }

    const int prevRank = (rank == 0) ? 0 : rank - 1;
    const int nextRank = (rank == CLUSTER - 1) ? rank : rank + 1;
    const float* prevS = (const float*)cluster.map_shared_rank((void*)sm, prevRank);
    const float* nextS = (const float*)cluster.map_shared_rank((void*)sm, nextRank);

    cluster.sync();   // all buffers zeroed cluster-wide

    float* outB = out + batch * kNT * kNREC;

    // one stencil phase over my H rows: hc = current level (kept),
    // hp = previous level (overwritten with the new one); results -> dbuf.
    auto phase = [&](const float* sbuf, float* dbuf,
                     float (&hc)[H], float (&hp)[H],
                     float ghTop, float ghBot, float inj) {
        float upB = topG ? ghTop : sbuf[(gr0 - 1) * kNX + c];
        float dnB = botG ? ghBot : sbuf[(gr0 + H) * kNX + c];
#pragma unroll
        for (int i = 0; i < H; i++) {
            float up  = (i == 0)     ? upB : hc[i - 1];
            float dn  = (i == H - 1) ? dnB : hc[i + 1];
            float l   = sbuf[(gr0 + i) * kNX + c - 1];
            float r   = sbuf[(gr0 + i) * kNX + c + 1];
            float lap = ((up + dn) + (l + r) - 4.0f * hc[i]) * kInvDH2;
            float hn  = fmaf(c2[i], lap, 2.0f * hc[i] - hp[i]);
            if (i == srcRow) hn += inj;
            hp[i] = hn;
            dbuf[(gr0 + i) * kNX + c] = hn;
        }
    };

    // Superstep s advances t=2s -> t+2 with ONE cluster.sync.
    // Rotation: cur=buf[t&3] (h^t), bufI=buf[(t+1)&3] (h^{t+1}),
    // bufO=buf[(t+2)&3] (h^{t+2}); bufO's old content (h^{t-2}) is dead, and
    // every cross-CTA read of step-s buffers completes before sync(s), whose
    // release/acquire orders it against the rewrite in superstep s+1/s+2.
    for (int s = 0; s < kNT / 2; s++) {
        const int t = 2 * s;
        const float* cur  = sm + (t & 3) * BUF;
        float*       bufI = sm + ((t + 1) & 3) * BUF;
        float*       bufO = sm + ((t + 2) & 3) * BUF;

        // ---- stage radius-2 remote halo (outer groups only) ----
        float a0 = 0.0f, a1 = 0.0f, ap = 0.0f;
        if (topG) {
            const float* pC = prevS + (t & 3) * BUF;
            const float* pP = prevS + ((t + 3) & 3) * BUF;
            a0 = pC[(kRows - 1) * kNX + c];   // h^t   row r0-1 (ghost center)
            a1 = pC[(kRows - 2) * kNX + c];   // h^t   row r0-2 (ghost's up)
            ap = pP[(kRows - 1) * kNX + c];   // h^t-1 row r0-1
            sm[SA + c] = a0;
        } else if (botG) {
            const float* nC = nextS + (t & 3) * BUF;
            const float* nP = nextS + ((t + 3) & 3) * BUF;
            a0 = nC[c];                       // h^t   row r0+kRows
            a1 = nC[kNX + c];                 // h^t   row r0+kRows+1
            ap = nP[c];                       // h^t-1 row r0+kRows
            sm[SB + c] = a0;
        }
        __syncthreads();                      // staged rows visible

        const float inj1 = kDT2 * sm[WAV + t];
        const float inj2 = kDT2 * sm[WAV + t + 1];

        // ---- ghost-row intermediate h^{t+1} (outer groups only, register) ----
        float extI = 0.0f;
        if (active && (topG || botG)) {
            const int stg = topG ? SA : SB;
            float adj = topG ? hE[0] : hE[H - 1];     // adjacent own row of h^t
            float vert = a1 + adj;                    // ghost's two vertical nbrs
            float lap  = (vert + (sm[stg + c - 1] + sm[stg + c + 1]) - 4.0f * a0) * kInvDH2;
            extI = fmaf(c2e, lap, 2.0f * a0 - ap);
            if (srcExt) extI += inj1;
        }

        // ---- phase 1: h^{t+1} on my rows ----
        if (active) phase(cur, bufI, hE, hO, a0, a0, inj1);
        __syncthreads();                      // bufI complete CTA-wide

        // receiver gather for step t (reads bufI, own CTA)
        if (tid < cnt)
            outB[t * kNREC + smi[RK + tid]] = bufI[smi[ROFF + tid]];

        // ---- phase 2: h^{t+2} on my rows (ghosts from extI registers) ----
        if (active) phase(bufI, bufO, hO, hE, extI, extI, inj2);

        cluster.sync();                       // publish bufI + bufO cluster-wide

        // receiver gather for step t+1 (bufO not rewritten until superstep s+2,
        // ordered after sync(s+1) > this read)
        if (tid < cnt)
            outB[(t + 1) * kNREC + smi[RK + tid]] = bufO[smi[ROFF + tid]];
    }
}

extern "C" void kernel_launch(void* const* d_in, const int* in_sizes, int n_in,
                              void* d_out, int out_size)
{
    (void)in_sizes; (void)n_in; (void)out_size;
    const float* x   = (const float*)d_in[0];
    const float* vp  = (const float*)d_in[1];
    const int*   src = (const int*)d_in[2];
    const int*   rec = (const int*)d_in[3];
    float*       out = (float*)d_out;

    cudaFuncSetAttribute(wave_fd_kernel<16>,
                         cudaFuncAttributeMaxDynamicSharedMemorySize, smem_bytes(16));
    cudaFuncSetAttribute(wave_fd_kernel<16>,
                         cudaFuncAttributeNonPortableClusterSizeAllowed, 1);
    cudaFuncSetAttribute(wave_fd_kernel<8>,
                         cudaFuncAttributeMaxDynamicSharedMemorySize, smem_bytes(8));

    int maxCluster = 0;
    {
        cudaLaunchConfig_t probe = {};
        probe.gridDim          = dim3(kB * 16, 1, 1);
        probe.blockDim         = dim3(kThreads, 1, 1);
        probe.dynamicSmemBytes = smem_bytes(16);
        cudaOccupancyMaxPotentialClusterSize(&maxCluster, (const void*)wave_fd_kernel<16>, &probe);
    }

    cudaLaunchAttribute attr[1];
    attr[0].id = cudaLaunchAttributeClusterDimension;
    attr[0].val.clusterDim.y = 1;
    attr[0].val.clusterDim.z = 1;

    cudaLaunchConfig_t cfg = {};
    cfg.blockDim = dim3(kThreads, 1, 1);
    cfg.stream   = 0;
    cfg.attrs    = attr;
    cfg.numAttrs = 1;

    if (maxCluster >= 16) {
        cfg.gridDim              = dim3(kB * 16, 1, 1);
        cfg.dynamicSmemBytes     = smem_bytes(16);
        attr[0].val.clusterDim.x = 16;
        cudaLaunchKernelEx(&cfg, wave_fd_kernel<16>, x, vp, src, rec, out);
    } else {
        cfg.gridDim              = dim3(kB * 8, 1, 1);
        cfg.dynamicSmemBytes     = smem_bytes(8);
        attr[0].val.clusterDim.x = 8;
        cudaLaunchKernelEx(&cfg, wave_fd_kernel<8>, x, vp, src, rec, out);
    }
}

// round 12
// speedup vs baseline: 1.4820x; 1.1501x over previous
#include <cuda_runtime.h>
#include <cooperative_groups.h>

namespace cg = cooperative_groups;

namespace {
constexpr int   kB       = 8;
constexpr int   kNT      = 256;
constexpr int   kNZ      = 256;
constexpr int   kNX      = 256;
constexpr int   kNREC    = 64;
constexpr int   kThreads = 512;               // column = tid&255, group = tid>>8
constexpr float kDT2     = 1.0e-6f;           // DT*DT
constexpr float kInvDH2  = 0.01f;             // 1/(DH*DH)

constexpr int smem_floats(int cluster) {
    int rows = kNZ / cluster;
    return 4 * rows * kNX + 512 + kNT + 64 + 64 + 4;
}
constexpr int smem_bytes(int cluster) { return smem_floats(cluster) * 4; }
}

template <int CLUSTER>
__global__ void __launch_bounds__(kThreads, 1)
wave_fd_kernel(const float* __restrict__ x,
               const float* __restrict__ vp,
               const int*   __restrict__ src_loc,
               const int*   __restrict__ rec_loc,
               float*       __restrict__ out)
{
    constexpr int kRows = kNZ / CLUSTER;      // rows per CTA
    constexpr int H     = kRows / 2;          // rows per thread
    constexpr int BUF   = kRows * kNX;        // floats per field buffer
    constexpr int SA    = 4 * BUF;            // staged prev-CTA row (kRows-1) of h^t
    constexpr int SB    = SA + 256;           // staged next-CTA row 0 of h^t
    constexpr int WAV   = SB + 256;
    constexpr int ROFF  = WAV + kNT;
    constexpr int RK    = ROFF + 64;
    constexpr int RCNT  = RK + 64;

    extern __shared__ float sm[];
    int* smi = (int*)sm;

    cg::cluster_group cluster = cg::this_cluster();
    const int rank  = (int)cluster.block_rank();
    const int batch = blockIdx.x / CLUSTER;
    const int tid   = threadIdx.x;
    const int c     = tid & (kNX - 1);        // column
    const int g     = tid >> 8;               // 0 = top half, 1 = bottom half
    const int r0    = rank * kRows;           // CTA's first global row
    const int gr0   = g * H;                  // my first local row
    const int gz0   = r0 + gr0;               // global

    // ---- init: zero all 4 field buffers + stage rows; wavelet; receiver list ----
    for (int i = tid; i < 4 * BUF + 512; i += kThreads) sm[i] = 0.0f;
    if (tid < kNT) sm[WAV + tid] = x[batch * kNT + tid];
    if (tid == 0) smi[RCNT] = 0;
    __syncthreads();
    if (tid < kNREC) {
        int rz = rec_loc[(batch * kNREC + tid) * 2 + 0];
        int rx = rec_loc[(batch * kNREC + tid) * 2 + 1];
        if (rz >= r0 && rz < r0 + kRows) {
            int slot = atomicAdd(&smi[RCNT], 1);
            smi[ROFF + slot] = (rz - r0) * kNX + rx;
            smi[RK   + slot] = tid;
        }
    }
    __syncthreads();
    const int cnt = smi[RCNT];

    // ---- source ownership (src is always interior: rows/cols 4..251) ----
    const int  sz = src_loc[batch * 2 + 0];
    const int  sx = src_loc[batch * 2 + 1];
    const bool isCol  = (c == sx);
    const int  srcRow = (isCol && sz >= gz0 && sz < gz0 + H) ? (sz - gz0) : -100;
    const bool srcExt = isCol && (g == 0 ? (sz == r0 - 1) : (sz == r0 + kRows));

    // ---- per-cell coefficients (c2=0 marks dead cells that stay 0 forever) ----
    float c2[H], c2e;
    const bool active = (c > 0) && (c < kNX - 1);
#pragma unroll
    for (int i = 0; i < H; i++) {
        int gz = gz0 + i;
        float v = vp[gz * kNX + c];
        bool dead = !active || gz == 0 || gz == kNZ - 1;
        c2[i] = dead ? 0.0f : v * v * kDT2;
    }
    {   // ghost-row coefficient (row r0-1 for g0, row r0+kRows for g1)
        int ge   = (g == 0) ? r0 - 1 : r0 + kRows;
        bool dE  = !active || ge <= 0 || ge >= kNZ - 1;
        int gec  = ge < 0 ? 0 : (ge > kNZ - 1 ? kNZ - 1 : ge);
        float ve = vp[gec * kNX + c];
        c2e = dE ? 0.0f : ve * ve * kDT2;
    }

    // ---- register-resident own rows: hE = even-time field, hO = odd-time field ----
    float hE[H], hO[H], extI = 0.0f;
#pragma unroll
    for (int i = 0; i < H; i++) { hE[i] = 0.0f; hO[i] = 0.0f; }

    const int prevRank = (rank == 0) ? 0 : rank - 1;
    const int nextRank = (rank == CLUSTER - 1) ? rank : rank + 1;
    const float* prevS = (const float*)cluster.map_shared_rank((void*)sm, prevRank);
    const float* nextS = (const float*)cluster.map_shared_rank((void*)sm, nextRank);

    cluster.sync();   // all buffers zeroed cluster-wide

    float* outB = out + batch * kNT * kNREC;

    // One stencil phase over my H rows.
    // KEY CHANGE vs r9: ALL smem loads are front-batched into registers BEFORE
    // the first store. sbuf/dbuf rotate through one buffer pool, so the
    // compiler cannot prove them distinct; interleaved load/store forced a
    // serialized LDS->STS->LDS chain per row. Batched: 18 back-to-back LDS
    // (MLP~18, one 29-cyc latency), then a pure FMA+STS loop.
    auto phase = [&](const float* sbuf, float* dbuf,
                     float (&hc)[H], float (&hp)[H],
                     float ghTop, float ghBot, float inj) {
        float lv[H], rv[H];
#pragma unroll
        for (int i = 0; i < H; i++) {
            lv[i] = sbuf[(gr0 + i) * kNX + c - 1];
            rv[i] = sbuf[(gr0 + i) * kNX + c + 1];
        }
        float upB = (g == 0) ? ghTop : sbuf[(gr0 - 1) * kNX + c];
        float dnB = (g == 1) ? ghBot : sbuf[(gr0 + H) * kNX + c];
#pragma unroll
        for (int i = 0; i < H; i++) {
            float up  = (i == 0)     ? upB : hc[i - 1];
            float dn  = (i == H - 1) ? dnB : hc[i + 1];
            float lap = ((up + dn) + (lv[i] + rv[i]) - 4.0f * hc[i]) * kInvDH2;
            float hn  = fmaf(c2[i], lap, 2.0f * hc[i] - hp[i]);
            if (i == srcRow) hn += inj;
            hp[i] = hn;
            dbuf[(gr0 + i) * kNX + c] = hn;
        }
    };

    // Superstep s advances t=2s -> t+2 with ONE cluster.sync.
    // Rotation: cur=buf[t&3] (h^t), bufI=buf[(t+1)&3] (h^{t+1}),
    // bufO=buf[(t+2)&3] (h^{t+2}); bufO's old content (h^{t-2}) is dead, and
    // every cross-CTA read of step-s buffers completes before sync(s), whose
    // release/acquire orders it against rewrites in later supersteps.
    for (int s = 0; s < kNT / 2; s++) {
        const int t = 2 * s;
        const float* cur  = sm + (t & 3) * BUF;
        float*       bufI = sm + ((t + 1) & 3) * BUF;
        float*       bufO = sm + ((t + 2) & 3) * BUF;

        // ---- stage radius-2 remote halo (3 values/thread; 1 row via smem for l/r) ----
        float a0, a1, ap;
        if (g == 0) {
            const float* pC = prevS + (t & 3) * BUF;
            const float* pP = prevS + ((t + 3) & 3) * BUF;
            a0 = pC[(kRows - 1) * kNX + c];   // h^t   row r0-1 (ghost center)
            a1 = pC[(kRows - 2) * kNX + c];   // h^t   row r0-2 (ghost's up)
            ap = pP[(kRows - 1) * kNX + c];   // h^t-1 row r0-1
            sm[SA + c] = a0;
        } else {
            const float* nC = nextS + (t & 3) * BUF;
            const float* nP = nextS + ((t + 3) & 3) * BUF;
            a0 = nC[c];                       // h^t   row r0+kRows
            a1 = nC[kNX + c];                 // h^t   row r0+kRows+1
            ap = nP[c];                       // h^t-1 row r0+kRows
            sm[SB + c] = a0;
        }
        __syncthreads();                      // staged rows visible

        const float inj1 = kDT2 * sm[WAV + t];
        const float inj2 = kDT2 * sm[WAV + t + 1];

        // ---- ghost-row intermediate h^{t+1} (register-only) ----
        if (active) {
            const int stg = (g == 0) ? SA : SB;
            float adj  = (g == 0) ? hE[0] : hE[H - 1];     // adjacent own row of h^t
            float lap  = ((a1 + adj) + (sm[stg + c - 1] + sm[stg + c + 1]) - 4.0f * a0) * kInvDH2;
            extI = fmaf(c2e, lap, 2.0f * a0 - ap);
            if (srcExt) extI += inj1;
        }

        // ---- phase 1: h^{t+1} on my rows ----
        if (active) phase(cur, bufI, hE, hO, a0, a0, inj1);
        __syncthreads();                      // bufI complete CTA-wide

        // receiver gather for step t (reads bufI, own CTA)
        if (tid < cnt)
            outB[t * kNREC + smi[RK + tid]] = bufI[smi[ROFF + tid]];

        // ---- phase 2: h^{t+2} on my rows (ghosts come from extI registers) ----
        if (active) phase(bufI, bufO, hO, hE, extI, extI, inj2);

        cluster.sync();   // publish bufI (h^{t+1}) + bufO (h^{t+2})

        // receiver gather for step t+1 (bufO not rewritten until superstep s+2,
        // which is ordered after sync(s+1) > this read)
        if (tid < cnt)
            outB[(t + 1) * kNREC + smi[RK + tid]] = bufO[smi[ROFF + tid]];
    }
}

extern "C" void kernel_launch(void* const* d_in, const int* in_sizes, int n_in,
                              void* d_out, int out_size)
{
    (void)in_sizes; (void)n_in; (void)out_size;
    const float* x   = (const float*)d_in[0];
    const float* vp  = (const float*)d_in[1];
    const int*   src = (const int*)d_in[2];
    const int*   rec = (const int*)d_in[3];
    float*       out = (float*)d_out;

    cudaFuncSetAttribute(wave_fd_kernel<16>,
                         cudaFuncAttributeMaxDynamicSharedMemorySize, smem_bytes(16));
    cudaFuncSetAttribute(wave_fd_kernel<16>,
                         cudaFuncAttributeNonPortableClusterSizeAllowed, 1);
    cudaFuncSetAttribute(wave_fd_kernel<8>,
                         cudaFuncAttributeMaxDynamicSharedMemorySize, smem_bytes(8));

    int maxCluster = 0;
    {
        cudaLaunchConfig_t probe = {};
        probe.gridDim          = dim3(kB * 16, 1, 1);
        probe.blockDim         = dim3(kThreads, 1, 1);
        probe.dynamicSmemBytes = smem_bytes(16);
        cudaOccupancyMaxPotentialClusterSize(&maxCluster, (const void*)wave_fd_kernel<16>, &probe);
    }

    cudaLaunchAttribute attr[1];
    attr[0].id = cudaLaunchAttributeClusterDimension;
    attr[0].val.clusterDim.y = 1;
    attr[0].val.clusterDim.z = 1;

    cudaLaunchConfig_t cfg = {};
    cfg.blockDim = dim3(kThreads, 1, 1);
    cfg.stream   = 0;
    cfg.attrs    = attr;
    cfg.numAttrs = 1;

    if (maxCluster >= 16) {
        cfg.gridDim              = dim3(kB * 16, 1, 1);
        cfg.dynamicSmemBytes     = smem_bytes(16);
        attr[0].val.clusterDim.x = 16;
        cudaLaunchKernelEx(&cfg, wave_fd_kernel<16>, x, vp, src, rec, out);
    } else {
        cfg.gridDim              = dim3(kB * 8, 1, 1);
        cfg.dynamicSmemBytes     = smem_bytes(8);
        attr[0].val.clusterDim.x = 8;
        cudaLaunchKernelEx(&cfg, wave_fd_kernel<8>, x, vp, src, rec, out);
    }
}

// round 13
// speedup vs baseline: 2.3326x; 1.5739x over previous
#include <cuda_runtime.h>
#include <cooperative_groups.h>

namespace cg = cooperative_groups;

namespace {
constexpr int   kB       = 8;
constexpr int   kNT      = 256;
constexpr int   kNZ      = 256;
constexpr int   kNX      = 256;
constexpr int   kNREC    = 64;
constexpr int   kThreads = 512;               // column = tid&255, group = tid>>8
constexpr float kDT2     = 1.0e-6f;           // DT*DT
constexpr float kInvDH2  = 0.01f;             // 1/(DH*DH)

constexpr int smem_floats(int cluster) {
    int rows = kNZ / cluster;
    return 4 * rows * kNX + 512 + kNT + 64 + 64 + 4;
}
constexpr int smem_bytes(int cluster) { return smem_floats(cluster) * 4; }
}

template <int CLUSTER>
__global__ void __launch_bounds__(kThreads, 1)
wave_fd_kernel(const float* __restrict__ x,
               const float* __restrict__ vp,
               const int*   __restrict__ src_loc,
               const int*   __restrict__ rec_loc,
               float*       __restrict__ out)
{
    constexpr int kRows = kNZ / CLUSTER;      // rows per CTA
    constexpr int H     = kRows / 2;          // rows per thread
    constexpr int BUF   = kRows * kNX;        // floats per field buffer
    constexpr int SA    = 4 * BUF;            // staged prev-CTA row (kRows-1) of h^t
    constexpr int SB    = SA + 256;           // staged next-CTA row 0 of h^t
    constexpr int WAV   = SB + 256;
    constexpr int ROFF  = WAV + kNT;
    constexpr int RK    = ROFF + 64;
    constexpr int RCNT  = RK + 64;

    extern __shared__ float sm[];
    int* smi = (int*)sm;

    cg::cluster_group cluster = cg::this_cluster();
    const int rank  = (int)cluster.block_rank();
    const int batch = blockIdx.x / CLUSTER;
    const int tid   = threadIdx.x;
    const int c     = tid & (kNX - 1);        // column
    const int g     = tid >> 8;               // 0 = top half, 1 = bottom half
    const int r0    = rank * kRows;           // CTA's first global row
    const int gr0   = g * H;                  // my first local row
    const int gz0   = r0 + gr0;               // global

    // ---- init: zero all 4 field buffers + stage rows; wavelet; receiver list ----
    for (int i = tid; i < 4 * BUF + 512; i += kThreads) sm[i] = 0.0f;
    if (tid < kNT) sm[WAV + tid] = x[batch * kNT + tid];
    if (tid == 0) smi[RCNT] = 0;
    __syncthreads();
    if (tid < kNREC) {
        int rz = rec_loc[(batch * kNREC + tid) * 2 + 0];
        int rx = rec_loc[(batch * kNREC + tid) * 2 + 1];
        if (rz >= r0 && rz < r0 + kRows) {
            int slot = atomicAdd(&smi[RCNT], 1);
            smi[ROFF + slot] = (rz - r0) * kNX + rx;
            smi[RK   + slot] = tid;
        }
    }
    __syncthreads();
    const int cnt = smi[RCNT];

    // ---- source ownership (src is always interior: rows/cols 4..251) ----
    const int  sz = src_loc[batch * 2 + 0];
    const int  sx = src_loc[batch * 2 + 1];
    const bool isCol  = (c == sx);
    const int  srcRow = (isCol && sz >= gz0 && sz < gz0 + H) ? (sz - gz0) : -100;
    const bool srcExt = isCol && (g == 0 ? (sz == r0 - 1) : (sz == r0 + kRows));

    // ---- per-cell coefficients with 1/dh^2 FOLDED IN (c2 = v^2*dt^2/dh^2).
    //      c2=0 marks dead cells that stay 0 forever. The laplacian in the
    //      hot loop stays UNSCALED, deleting one FMUL per cell. ----
    const float kCF = kDT2 * kInvDH2;
    float c2[H], c2e;
    const bool active = (c > 0) && (c < kNX - 1);
#pragma unroll
    for (int i = 0; i < H; i++) {
        int gz = gz0 + i;
        float v = vp[gz * kNX + c];
        bool dead = !active || gz == 0 || gz == kNZ - 1;
        c2[i] = dead ? 0.0f : v * v * kCF;
    }
    {   // ghost-row coefficient (row r0-1 for g0, row r0+kRows for g1)
        int ge   = (g == 0) ? r0 - 1 : r0 + kRows;
        bool dE  = !active || ge <= 0 || ge >= kNZ - 1;
        int gec  = ge < 0 ? 0 : (ge > kNZ - 1 ? kNZ - 1 : ge);
        float ve = vp[gec * kNX + c];
        c2e = dE ? 0.0f : ve * ve * kCF;
    }

    // ---- register-resident own rows: hE = even-time field, hO = odd-time field ----
    float hE[H], hO[H], extI = 0.0f;
#pragma unroll
    for (int i = 0; i < H; i++) { hE[i] = 0.0f; hO[i] = 0.0f; }

    const int prevRank = (rank == 0) ? 0 : rank - 1;
    const int nextRank = (rank == CLUSTER - 1) ? rank : rank + 1;
    const float* prevS = (const float*)cluster.map_shared_rank((void*)sm, prevRank);
    const float* nextS = (const float*)cluster.map_shared_rank((void*)sm, nextRank);

    cluster.sync();   // all buffers zeroed cluster-wide

    float* outB = out + batch * kNT * kNREC;

    // One stencil phase over my H rows — IDENTICAL memory schedule to the
    // 253.7us champion (interleaved LDS/FMA/STS); only the FP-op count per
    // cell is reduced (unscaled laplacian + single-op fma forms).
    auto phase = [&](const float* sbuf, float* dbuf,
                     float (&hc)[H], float (&hp)[H],
                     float ghTop, float ghBot, float inj) {
        float upB = (g == 0) ? ghTop : sbuf[(gr0 - 1) * kNX + c];
        float dnB = (g == 1) ? ghBot : sbuf[(gr0 + H) * kNX + c];
#pragma unroll
        for (int i = 0; i < H; i++) {
            float up  = (i == 0)     ? upB : hc[i - 1];
            float dn  = (i == H - 1) ? dnB : hc[i + 1];
            float l   = sbuf[(gr0 + i) * kNX + c - 1];
            float r   = sbuf[(gr0 + i) * kNX + c + 1];
            float s   = (up + dn) + (l + r);
            float lapU = fmaf(hc[i], -4.0f, s);          // unscaled laplacian
            float base = fmaf(2.0f, hc[i], -hp[i]);      // 2h - h_prev (1 op)
            float hn   = fmaf(c2[i], lapU, base);        // c2 carries dt^2/dh^2
            if (i == srcRow) hn += inj;
            hp[i] = hn;
            dbuf[(gr0 + i) * kNX + c] = hn;
        }
    };

    // Superstep s advances t=2s -> t+2 with ONE cluster.sync.
    // Rotation: cur=buf[t&3] (h^t), bufI=buf[(t+1)&3] (h^{t+1}),
    // bufO=buf[(t+2)&3] (h^{t+2}); bufO's old content (h^{t-2}) is dead, and
    // every cross-CTA read of step-s buffers completes before sync(s), whose
    // release/acquire orders it against rewrites in later supersteps.
    for (int s = 0; s < kNT / 2; s++) {
        const int t = 2 * s;
        const float* cur  = sm + (t & 3) * BUF;
        float*       bufI = sm + ((t + 1) & 3) * BUF;
        float*       bufO = sm + ((t + 2) & 3) * BUF;

        // ---- stage radius-2 remote halo (3 values/thread; 1 row via smem for l/r) ----
        float a0, a1, ap;
        if (g == 0) {
            const float* pC = prevS + (t & 3) * BUF;
            const float* pP = prevS + ((t + 3) & 3) * BUF;
            a0 = pC[(kRows - 1) * kNX + c];   // h^t   row r0-1 (ghost center)
            a1 = pC[(kRows - 2) * kNX + c];   // h^t   row r0-2 (ghost's up)
            ap = pP[(kRows - 1) * kNX + c];   // h^t-1 row r0-1
            sm[SA + c] = a0;
        } else {
            const float* nC = nextS + (t & 3) * BUF;
            const float* nP = nextS + ((t + 3) & 3) * BUF;
            a0 = nC[c];                       // h^t   row r0+kRows
            a1 = nC[kNX + c];                 // h^t   row r0+kRows+1
            ap = nP[c];                       // h^t-1 row r0+kRows
            sm[SB + c] = a0;
        }
        __syncthreads();                      // staged rows visible

        const float inj1 = kDT2 * sm[WAV + t];
        const float inj2 = kDT2 * sm[WAV + t + 1];

        // ---- ghost-row intermediate h^{t+1} (register-only, folded coeff) ----
        if (active) {
            const int stg = (g == 0) ? SA : SB;
            float adj  = (g == 0) ? hE[0] : hE[H - 1];     // adjacent own row of h^t
            float s0   = (a1 + adj) + (sm[stg + c - 1] + sm[stg + c + 1]);
            float lapU = fmaf(a0, -4.0f, s0);
            extI = fmaf(c2e, lapU, fmaf(2.0f, a0, -ap));
            if (srcExt) extI += inj1;
        }

        // ---- phase 1: h^{t+1} on my rows ----
        if (active) phase(cur, bufI, hE, hO, a0, a0, inj1);
        __syncthreads();                      // bufI complete CTA-wide

        // receiver gather for step t (reads bufI, own CTA)
        if (tid < cnt)
            outB[t * kNREC + smi[RK + tid]] = bufI[smi[ROFF + tid]];

        // ---- phase 2: h^{t+2} on my rows (ghosts come from extI registers) ----
        if (active) phase(bufI, bufO, hO, hE, extI, extI, inj2);

        cluster.sync();   // publish bufI (h^{t+1}) + bufO (h^{t+2})

        // receiver gather for step t+1 (bufO not rewritten until superstep s+2,
        // which is ordered after sync(s+1) > this read)
        if (tid < cnt)
            outB[(t + 1) * kNREC + smi[RK + tid]] = bufO[smi[ROFF + tid]];
    }
}

extern "C" void kernel_launch(void* const* d_in, const int* in_sizes, int n_in,
                              void* d_out, int out_size)
{
    (void)in_sizes; (void)n_in; (void)out_size;
    const float* x   = (const float*)d_in[0];
    const float* vp  = (const float*)d_in[1];
    const int*   src = (const int*)d_in[2];
    const int*   rec = (const int*)d_in[3];
    float*       out = (float*)d_out;

    cudaFuncSetAttribute(wave_fd_kernel<16>,
                         cudaFuncAttributeMaxDynamicSharedMemorySize, smem_bytes(16));
    cudaFuncSetAttribute(wave_fd_kernel<16>,
                         cudaFuncAttributeNonPortableClusterSizeAllowed, 1);
    cudaFuncSetAttribute(wave_fd_kernel<8>,
                         cudaFuncAttributeMaxDynamicSharedMemorySize, smem_bytes(8));

    int maxCluster = 0;
    {
        cudaLaunchConfig_t probe = {};
        probe.gridDim          = dim3(kB * 16, 1, 1);
        probe.blockDim         = dim3(kThreads, 1, 1);
        probe.dynamicSmemBytes = smem_bytes(16);
        cudaOccupancyMaxPotentialClusterSize(&maxCluster, (const void*)wave_fd_kernel<16>, &probe);
    }

    cudaLaunchAttribute attr[1];
    attr[0].id = cudaLaunchAttributeClusterDimension;
    attr[0].val.clusterDim.y = 1;
    attr[0].val.clusterDim.z = 1;

    cudaLaunchConfig_t cfg = {};
    cfg.blockDim = dim3(kThreads, 1, 1);
    cfg.stream   = 0;
    cfg.attrs    = attr;
    cfg.numAttrs = 1;

    if (maxCluster >= 16) {
        cfg.gridDim              = dim3(kB * 16, 1, 1);
        cfg.dynamicSmemBytes     = smem_bytes(16);
        attr[0].val.clusterDim.x = 16;
        cudaLaunchKernelEx(&cfg, wave_fd_kernel<16>, x, vp, src, rec, out);
    } else {
        cfg.gridDim              = dim3(kB * 8, 1, 1);
        cfg.dynamicSmemBytes     = smem_bytes(8);
        attr[0].val.clusterDim.x = 8;
        cudaLaunchKernelEx(&cfg, wave_fd_kernel<8>, x, vp, src, rec, out);
    }
}